// round 2
// baseline (speedup 1.0000x reference)
#include <cuda_runtime.h>

#define BB 2
#define NN 4096
#define DD 512
#define HH 8
#define HD 64
#define NH (BB*HH)          // 16
#define MTOT (BB*NN)        // 8192
#define SCALE 0.125f

// Scratch (allocation-free rule: __device__ globals)
__device__ float g_q[NH * NN * HD];
__device__ float g_k[NH * NN * HD];
__device__ float g_v[NH * NN * HD];
__device__ float g_ctx[MTOT * DD];

// ---------------------------------------------------------------------------
// Kernel 1: QKV GEMM.  C[m][n] = sum_k x[m][k] * w_qkv[n][k]
// M=8192, N=1536, K=512. 128x128 tile, BK=8, 256 threads, 8x8 microtile.
// Epilogue scatters into g_q/g_k/g_v laid out [B,H,N,Hd].
// ---------------------------------------------------------------------------
__global__ __launch_bounds__(256) void qkv_gemm(const float* __restrict__ x,
                                                const float* __restrict__ w) {
    __shared__ float As[8][128];
    __shared__ float Bs[8][128];
    const int tid = threadIdx.x;
    const int m0 = blockIdx.y * 128;
    const int n0 = blockIdx.x * 128;
    const int tx = tid & 15;
    const int ty = tid >> 4;

    float acc[8][8];
#pragma unroll
    for (int i = 0; i < 8; i++)
#pragma unroll
        for (int j = 0; j < 8; j++) acc[i][j] = 0.f;

    const int lr = tid >> 1;   // 0..127
    const int lk4 = tid & 1;   // 0..1
    const float* xa = x + (m0 + lr) * DD + lk4 * 4;
    const float* wb = w + (n0 + lr) * DD + lk4 * 4;

    for (int k0 = 0; k0 < DD; k0 += 8) {
        float4 av = *(const float4*)(xa + k0);
        float4 bv = *(const float4*)(wb + k0);
        As[lk4 * 4 + 0][lr] = av.x; As[lk4 * 4 + 1][lr] = av.y;
        As[lk4 * 4 + 2][lr] = av.z; As[lk4 * 4 + 3][lr] = av.w;
        Bs[lk4 * 4 + 0][lr] = bv.x; Bs[lk4 * 4 + 1][lr] = bv.y;
        Bs[lk4 * 4 + 2][lr] = bv.z; Bs[lk4 * 4 + 3][lr] = bv.w;
        __syncthreads();
#pragma unroll
        for (int k = 0; k < 8; k++) {
            float4 a0 = *(const float4*)&As[k][ty * 8];
            float4 a1 = *(const float4*)&As[k][ty * 8 + 4];
            float4 b0 = *(const float4*)&Bs[k][tx * 8];
            float4 b1 = *(const float4*)&Bs[k][tx * 8 + 4];
            float a[8] = {a0.x, a0.y, a0.z, a0.w, a1.x, a1.y, a1.z, a1.w};
            float b[8] = {b0.x, b0.y, b0.z, b0.w, b1.x, b1.y, b1.z, b1.w};
#pragma unroll
            for (int i = 0; i < 8; i++)
#pragma unroll
                for (int j = 0; j < 8; j++) acc[i][j] += a[i] * b[j];
        }
        __syncthreads();
    }

    // scatter epilogue: col n -> (three, h, hd); row m -> (b, seq)
#pragma unroll
    for (int i = 0; i < 8; i++) {
        int m = m0 + ty * 8 + i;
        int b = m >> 12;
        int seq = m & (NN - 1);
#pragma unroll
        for (int j = 0; j < 8; j++) {
            int n = n0 + tx * 8 + j;
            int three = n >> 9;
            int h = (n >> 6) & 7;
            int hd = n & 63;
            float* dst = (three == 0) ? g_q : (three == 1) ? g_k : g_v;
            dst[((b * HH + h) * NN + seq) * HD + hd] = acc[i][j];
        }
    }
}

// ---------------------------------------------------------------------------
// Kernel 2: flash attention, fp32. One CTA per (bh, 64-row q tile).
// 256 threads = 16x16 grid, 4x4 microtile over 64x64 S tile.
// Q/K stored d-major (transposed) in smem with xor swizzle at float4 grain;
// V/P stored row-major with pad 68.
// ---------------------------------------------------------------------------
#define PROW 68

__global__ __launch_bounds__(256) void attn_kernel() {
    extern __shared__ float sm[];
    float* Qs = sm;                 // 64*64, swizzled, d-major
    float* Ks = sm + 64 * 64;       // 64*64, swizzled, d-major
    float* Vs = sm + 2 * 64 * 64;   // 64*PROW, kv-major
    float* Ps = Vs + 64 * PROW;     // 64*PROW, row-major

    const int tid = threadIdx.x;
    const int tx = tid & 15;
    const int ty = tid >> 4;
    const int bh = blockIdx.y;
    const int qt = blockIdx.x;

    const float* qbase = g_q + (bh * NN + qt * 64) * HD;
    const float* kbase = g_k + bh * NN * HD;
    const float* vbase = g_v + bh * NN * HD;

    // Load Q transposed+swizzled, pre-scaled by SCALE
#pragma unroll
    for (int it = 0; it < 4; it++) {
        int idx = tid + 256 * it;
        int r = idx >> 4;          // 0..63 (q row)
        int d4 = idx & 15;         // float4 index along d
        float4 qv = *(const float4*)(qbase + r * HD + d4 * 4);
        float vals[4] = {qv.x * SCALE, qv.y * SCALE, qv.z * SCALE, qv.w * SCALE};
#pragma unroll
        for (int c = 0; c < 4; c++) {
            int row = 4 * d4 + c;                       // d index
            int pc4 = (r >> 2) ^ ((row >> 2) & 7);      // swizzled col4
            Qs[row * 64 + pc4 * 4 + (r & 3)] = vals[c];
        }
    }

    float o[4][4];
    float mo[4], l[4];
#pragma unroll
    for (int i = 0; i < 4; i++) {
        mo[i] = -1e30f; l[i] = 0.f;
#pragma unroll
        for (int j = 0; j < 4; j++) o[i][j] = 0.f;
    }

    for (int kt = 0; kt < NN / 64; kt++) {
        __syncthreads();   // previous PV done before overwriting K/V
        const float* kb = kbase + kt * 64 * HD;
        const float* vb = vbase + kt * 64 * HD;
#pragma unroll
        for (int it = 0; it < 4; it++) {
            int idx = tid + 256 * it;
            int r = idx >> 4;
            int d4 = idx & 15;
            float4 kv = *(const float4*)(kb + r * HD + d4 * 4);
            float kvals[4] = {kv.x, kv.y, kv.z, kv.w};
#pragma unroll
            for (int c = 0; c < 4; c++) {
                int row = 4 * d4 + c;
                int pc4 = (r >> 2) ^ ((row >> 2) & 7);
                Ks[row * 64 + pc4 * 4 + (r & 3)] = kvals[c];
            }
            float4 vv = *(const float4*)(vb + r * HD + d4 * 4);
            *(float4*)&Vs[r * PROW + d4 * 4] = vv;
        }
        __syncthreads();

        // S = Q K^T (scaled): outer product over d
        float s[4][4];
#pragma unroll
        for (int i = 0; i < 4; i++)
#pragma unroll
            for (int j = 0; j < 4; j++) s[i][j] = 0.f;

#pragma unroll 16
        for (int d = 0; d < 64; d++) {
            int sw = (d >> 2) & 7;
            float4 q4 = *(const float4*)&Qs[d * 64 + ((ty ^ sw) << 2)];
            float4 k4 = *(const float4*)&Ks[d * 64 + ((tx ^ sw) << 2)];
            s[0][0] += q4.x * k4.x; s[0][1] += q4.x * k4.y; s[0][2] += q4.x * k4.z; s[0][3] += q4.x * k4.w;
            s[1][0] += q4.y * k4.x; s[1][1] += q4.y * k4.y; s[1][2] += q4.y * k4.z; s[1][3] += q4.y * k4.w;
            s[2][0] += q4.z * k4.x; s[2][1] += q4.z * k4.y; s[2][2] += q4.z * k4.z; s[2][3] += q4.z * k4.w;
            s[3][0] += q4.w * k4.x; s[3][1] += q4.w * k4.y; s[3][2] += q4.w * k4.z; s[3][3] += q4.w * k4.w;
        }

        // streaming softmax (row groups = 16 lanes sharing ty)
#pragma unroll
        for (int i = 0; i < 4; i++) {
            float mx = fmaxf(fmaxf(s[i][0], s[i][1]), fmaxf(s[i][2], s[i][3]));
            mx = fmaxf(mx, __shfl_xor_sync(0xffffffffu, mx, 1));
            mx = fmaxf(mx, __shfl_xor_sync(0xffffffffu, mx, 2));
            mx = fmaxf(mx, __shfl_xor_sync(0xffffffffu, mx, 4));
            mx = fmaxf(mx, __shfl_xor_sync(0xffffffffu, mx, 8));
            float mnew = fmaxf(mo[i], mx);
            float corr = __expf(mo[i] - mnew);
            float rs = 0.f;
#pragma unroll
            for (int j = 0; j < 4; j++) {
                s[i][j] = __expf(s[i][j] - mnew);
                rs += s[i][j];
            }
            rs += __shfl_xor_sync(0xffffffffu, rs, 1);
            rs += __shfl_xor_sync(0xffffffffu, rs, 2);
            rs += __shfl_xor_sync(0xffffffffu, rs, 4);
            rs += __shfl_xor_sync(0xffffffffu, rs, 8);
            l[i] = l[i] * corr + rs;
#pragma unroll
            for (int j = 0; j < 4; j++) o[i][j] *= corr;
            mo[i] = mnew;
            *(float4*)&Ps[(ty * 4 + i) * PROW + tx * 4] =
                make_float4(s[i][0], s[i][1], s[i][2], s[i][3]);
        }
        __syncthreads();

        // O += P @ V
#pragma unroll 8
        for (int kv = 0; kv < 64; kv++) {
            float4 v4 = *(const float4*)&Vs[kv * PROW + tx * 4];
            const float* prow = &Ps[ty * 4 * PROW + kv];
#pragma unroll
            for (int i = 0; i < 4; i++) {
                float p = prow[i * PROW];
                o[i][0] += p * v4.x; o[i][1] += p * v4.y;
                o[i][2] += p * v4.z; o[i][3] += p * v4.w;
            }
        }
    }

    // epilogue: ctx[b][seq][h*64 + col] = O / l
    const int b = bh >> 3;
    const int h = bh & 7;
#pragma unroll
    for (int i = 0; i < 4; i++) {
        int seq = qt * 64 + ty * 4 + i;
        float inv = 1.0f / l[i];
        float4 ov = make_float4(o[i][0] * inv, o[i][1] * inv,
                                o[i][2] * inv, o[i][3] * inv);
        *(float4*)(g_ctx + (b * NN + seq) * DD + h * HD + tx * 4) = ov;
    }
}

// ---------------------------------------------------------------------------
// Kernel 3: output projection.  out[m][n] = sum_k ctx[m][k]*w_proj[n][k] + b[n]
// M=8192, N=512, K=512.
// ---------------------------------------------------------------------------
__global__ __launch_bounds__(256) void proj_gemm(const float* __restrict__ w,
                                                 const float* __restrict__ bias,
                                                 float* __restrict__ out) {
    __shared__ float As[8][128];
    __shared__ float Bs[8][128];
    const int tid = threadIdx.x;
    const int m0 = blockIdx.y * 128;
    const int n0 = blockIdx.x * 128;
    const int tx = tid & 15;
    const int ty = tid >> 4;

    float acc[8][8];
#pragma unroll
    for (int i = 0; i < 8; i++)
#pragma unroll
        for (int j = 0; j < 8; j++) acc[i][j] = 0.f;

    const int lr = tid >> 1;
    const int lk4 = tid & 1;
    const float* xa = g_ctx + (m0 + lr) * DD + lk4 * 4;
    const float* wb = w + (n0 + lr) * DD + lk4 * 4;

    for (int k0 = 0; k0 < DD; k0 += 8) {
        float4 av = *(const float4*)(xa + k0);
        float4 bv = *(const float4*)(wb + k0);
        As[lk4 * 4 + 0][lr] = av.x; As[lk4 * 4 + 1][lr] = av.y;
        As[lk4 * 4 + 2][lr] = av.z; As[lk4 * 4 + 3][lr] = av.w;
        Bs[lk4 * 4 + 0][lr] = bv.x; Bs[lk4 * 4 + 1][lr] = bv.y;
        Bs[lk4 * 4 + 2][lr] = bv.z; Bs[lk4 * 4 + 3][lr] = bv.w;
        __syncthreads();
#pragma unroll
        for (int k = 0; k < 8; k++) {
            float4 a0 = *(const float4*)&As[k][ty * 8];
            float4 a1 = *(const float4*)&As[k][ty * 8 + 4];
            float4 b0 = *(const float4*)&Bs[k][tx * 8];
            float4 b1 = *(const float4*)&Bs[k][tx * 8 + 4];
            float a[8] = {a0.x, a0.y, a0.z, a0.w, a1.x, a1.y, a1.z, a1.w};
            float b[8] = {b0.x, b0.y, b0.z, b0.w, b1.x, b1.y, b1.z, b1.w};
#pragma unroll
            for (int i = 0; i < 8; i++)
#pragma unroll
                for (int j = 0; j < 8; j++) acc[i][j] += a[i] * b[j];
        }
        __syncthreads();
    }

#pragma unroll
    for (int i = 0; i < 8; i++) {
        int m = m0 + ty * 8 + i;
#pragma unroll
        for (int j = 0; j < 8; j++) {
            int n = n0 + tx * 8 + j;
            out[m * DD + n] = acc[i][j] + bias[n];
        }
    }
}

// ---------------------------------------------------------------------------

extern "C" void kernel_launch(void* const* d_in, const int* in_sizes, int n_in,
                              void* d_out, int out_size) {
    const float* x      = (const float*)d_in[0];
    const float* w_qkv  = (const float*)d_in[1];
    const float* w_proj = (const float*)d_in[2];
    const float* b_proj = (const float*)d_in[3];
    float* out = (float*)d_out;

    qkv_gemm<<<dim3(1536 / 128, MTOT / 128), 256>>>(x, w_qkv);

    const int attn_smem = (2 * 64 * 64 + 2 * 64 * PROW) * sizeof(float); // 67584 B
    cudaFuncSetAttribute(attn_kernel, cudaFuncAttributeMaxDynamicSharedMemorySize,
                         attn_smem);
    attn_kernel<<<dim3(NN / 64, NH), 256, attn_smem>>>();

    proj_gemm<<<dim3(DD / 128, MTOT / 128), 256>>>(w_proj, b_proj, out);
}

// round 3
// speedup vs baseline: 2.0422x; 2.0422x over previous
#include <cuda_runtime.h>
#include <cstdint>

#define BB 2
#define NN 4096
#define DD 512
#define HH 8
#define HD 64
#define NH (BB*HH)          // 16
#define MTOT (BB*NN)        // 8192
#define SCALE 0.125f

// Scratch (allocation-free rule: __device__ globals)
__device__ float g_q[NH * NN * HD];
__device__ float g_k[NH * NN * HD];
__device__ float g_v[NH * NN * HD];
__device__ float g_ctx[MTOT * DD];

// ---------------------------------------------------------------------------
// mma.sync tf32 primitives (m16n8k8, row.col, fp32 accum)
// ---------------------------------------------------------------------------
__device__ __forceinline__ uint32_t f2tf32(float f) {
    uint32_t r;
    asm("cvt.rna.tf32.f32 %0, %1;\n" : "=r"(r) : "f"(f));
    return r;
}

__device__ __forceinline__ void mma_tf32(float c[4], const uint32_t a[4],
                                         uint32_t b0, uint32_t b1) {
    asm volatile(
        "mma.sync.aligned.m16n8k8.row.col.f32.tf32.tf32.f32 "
        "{%0,%1,%2,%3}, {%4,%5,%6,%7}, {%8,%9}, {%0,%1,%2,%3};\n"
        : "+f"(c[0]), "+f"(c[1]), "+f"(c[2]), "+f"(c[3])
        : "r"(a[0]), "r"(a[1]), "r"(a[2]), "r"(a[3]), "r"(b0), "r"(b1));
}

// ---------------------------------------------------------------------------
// Kernel 1: QKV GEMM (fp32 SIMT, proven).  C[m][n] = sum_k x[m][k]*w[n][k]
// ---------------------------------------------------------------------------
__global__ __launch_bounds__(256) void qkv_gemm(const float* __restrict__ x,
                                                const float* __restrict__ w) {
    __shared__ float As[8][128];
    __shared__ float Bs[8][128];
    const int tid = threadIdx.x;
    const int m0 = blockIdx.y * 128;
    const int n0 = blockIdx.x * 128;
    const int tx = tid & 15;
    const int ty = tid >> 4;

    float acc[8][8];
#pragma unroll
    for (int i = 0; i < 8; i++)
#pragma unroll
        for (int j = 0; j < 8; j++) acc[i][j] = 0.f;

    const int lr = tid >> 1;
    const int lk4 = tid & 1;
    const float* xa = x + (m0 + lr) * DD + lk4 * 4;
    const float* wb = w + (n0 + lr) * DD + lk4 * 4;

    for (int k0 = 0; k0 < DD; k0 += 8) {
        float4 av = *(const float4*)(xa + k0);
        float4 bv = *(const float4*)(wb + k0);
        As[lk4 * 4 + 0][lr] = av.x; As[lk4 * 4 + 1][lr] = av.y;
        As[lk4 * 4 + 2][lr] = av.z; As[lk4 * 4 + 3][lr] = av.w;
        Bs[lk4 * 4 + 0][lr] = bv.x; Bs[lk4 * 4 + 1][lr] = bv.y;
        Bs[lk4 * 4 + 2][lr] = bv.z; Bs[lk4 * 4 + 3][lr] = bv.w;
        __syncthreads();
#pragma unroll
        for (int k = 0; k < 8; k++) {
            float4 a0 = *(const float4*)&As[k][ty * 8];
            float4 a1 = *(const float4*)&As[k][ty * 8 + 4];
            float4 b0 = *(const float4*)&Bs[k][tx * 8];
            float4 b1 = *(const float4*)&Bs[k][tx * 8 + 4];
            float a[8] = {a0.x, a0.y, a0.z, a0.w, a1.x, a1.y, a1.z, a1.w};
            float b[8] = {b0.x, b0.y, b0.z, b0.w, b1.x, b1.y, b1.z, b1.w};
#pragma unroll
            for (int i = 0; i < 8; i++)
#pragma unroll
                for (int j = 0; j < 8; j++) acc[i][j] += a[i] * b[j];
        }
        __syncthreads();
    }

#pragma unroll
    for (int i = 0; i < 8; i++) {
        int m = m0 + ty * 8 + i;
        int b = m >> 12;
        int seq = m & (NN - 1);
#pragma unroll
        for (int j = 0; j < 8; j++) {
            int n = n0 + tx * 8 + j;
            int three = n >> 9;
            int h = (n >> 6) & 7;
            int hd = n & 63;
            float* dst = (three == 0) ? g_q : (three == 1) ? g_k : g_v;
            dst[((b * HH + h) * NN + seq) * HD + hd] = acc[i][j];
        }
    }
}

// ---------------------------------------------------------------------------
// Kernel 2: flash attention with tf32 mma.sync.
// CTA: 256 threads = 8 warps; 128 q rows per CTA (16 per warp); kv tile 64.
// K/V stored tf32 in smem; softmax in C-fragment registers; P->A fragment
// conversion done with intra-quad shuffles (no smem round trip).
// ---------------------------------------------------------------------------
#define KT 64
#define QT 128
#define KSTR 68   // words; bank = 4g+t  -> conflict-free B-frag loads
#define VSTR 72   // words; bank = 8t+g  -> conflict-free B-frag loads

__global__ __launch_bounds__(256, 2) void attn_mma() {
    __shared__ uint32_t Ks[KT * KSTR];   // [kv][d] tf32
    __shared__ uint32_t Vs[KT * VSTR];   // [kv][d] tf32

    const int tid  = threadIdx.x;
    const int lane = tid & 31;
    const int w    = tid >> 5;      // warp 0..7
    const int g    = lane >> 2;     // group row 0..7
    const int t    = lane & 3;      // thread-in-group

    const int bh = blockIdx.y;
    const int qt = blockIdx.x;

    const float* qbase = g_q + (size_t)(bh * NN + qt * QT + w * 16) * HD;
    const float* kbase = g_k + (size_t)bh * NN * HD;
    const float* vbase = g_v + (size_t)bh * NN * HD;

    // Q fragments (A operand), pre-scaled: qf[k-step][4]
    uint32_t qf[8][4];
#pragma unroll
    for (int j = 0; j < 8; j++) {
        qf[j][0] = f2tf32(qbase[g       * HD + 8 * j + t]     * SCALE);
        qf[j][1] = f2tf32(qbase[(g + 8) * HD + 8 * j + t]     * SCALE);
        qf[j][2] = f2tf32(qbase[g       * HD + 8 * j + t + 4] * SCALE);
        qf[j][3] = f2tf32(qbase[(g + 8) * HD + 8 * j + t + 4] * SCALE);
    }

    float o[8][4];
#pragma unroll
    for (int n = 0; n < 8; n++)
#pragma unroll
        for (int i = 0; i < 4; i++) o[n][i] = 0.f;
    float mo0 = -1e30f, mo1 = -1e30f;
    float l0 = 0.f, l1 = 0.f;

    for (int ktile = 0; ktile < NN / KT; ktile++) {
        __syncthreads();   // previous iteration's smem reads complete
        const float* kb = kbase + (size_t)ktile * KT * HD;
        const float* vb = vbase + (size_t)ktile * KT * HD;
#pragma unroll
        for (int it = 0; it < 4; it++) {
            int idx = tid + 256 * it;     // 0..1023
            int r = idx >> 4;             // kv row 0..63
            int c4 = idx & 15;            // float4 col
            float4 k4 = *(const float4*)(kb + r * HD + c4 * 4);
            uint4 kk;
            kk.x = f2tf32(k4.x); kk.y = f2tf32(k4.y);
            kk.z = f2tf32(k4.z); kk.w = f2tf32(k4.w);
            *(uint4*)&Ks[r * KSTR + c4 * 4] = kk;
            float4 v4 = *(const float4*)(vb + r * HD + c4 * 4);
            uint4 vv;
            vv.x = f2tf32(v4.x); vv.y = f2tf32(v4.y);
            vv.z = f2tf32(v4.z); vv.w = f2tf32(v4.w);
            *(uint4*)&Vs[r * VSTR + c4 * 4] = vv;
        }
        __syncthreads();

        // S = Q K^T  (16 x 64 per warp)
        float s[8][4];
#pragma unroll
        for (int n = 0; n < 8; n++)
#pragma unroll
            for (int i = 0; i < 4; i++) s[n][i] = 0.f;

#pragma unroll
        for (int j = 0; j < 8; j++) {          // k-step over d
#pragma unroll
            for (int n = 0; n < 8; n++) {      // n-tile over kv
                uint32_t b0 = Ks[(n * 8 + g) * KSTR + 8 * j + t];
                uint32_t b1 = Ks[(n * 8 + g) * KSTR + 8 * j + t + 4];
                mma_tf32(s[n], qf[j], b0, b1);
            }
        }

        // online softmax in C-fragment registers.
        // regs 0,1 -> row g; regs 2,3 -> row g+8. Row spread over 4 lanes.
        float mx0 = -1e30f, mx1 = -1e30f;
#pragma unroll
        for (int n = 0; n < 8; n++) {
            mx0 = fmaxf(mx0, fmaxf(s[n][0], s[n][1]));
            mx1 = fmaxf(mx1, fmaxf(s[n][2], s[n][3]));
        }
        mx0 = fmaxf(mx0, __shfl_xor_sync(0xffffffffu, mx0, 1));
        mx0 = fmaxf(mx0, __shfl_xor_sync(0xffffffffu, mx0, 2));
        mx1 = fmaxf(mx1, __shfl_xor_sync(0xffffffffu, mx1, 1));
        mx1 = fmaxf(mx1, __shfl_xor_sync(0xffffffffu, mx1, 2));

        float mn0 = fmaxf(mo0, mx0);
        float mn1 = fmaxf(mo1, mx1);
        float corr0 = __expf(mo0 - mn0);
        float corr1 = __expf(mo1 - mn1);
        float rs0 = 0.f, rs1 = 0.f;
#pragma unroll
        for (int n = 0; n < 8; n++) {
            s[n][0] = __expf(s[n][0] - mn0);
            s[n][1] = __expf(s[n][1] - mn0);
            s[n][2] = __expf(s[n][2] - mn1);
            s[n][3] = __expf(s[n][3] - mn1);
            rs0 += s[n][0] + s[n][1];
            rs1 += s[n][2] + s[n][3];
        }
        rs0 += __shfl_xor_sync(0xffffffffu, rs0, 1);
        rs0 += __shfl_xor_sync(0xffffffffu, rs0, 2);
        rs1 += __shfl_xor_sync(0xffffffffu, rs1, 1);
        rs1 += __shfl_xor_sync(0xffffffffu, rs1, 2);
        l0 = l0 * corr0 + rs0;
        l1 = l1 * corr1 + rs1;
        mo0 = mn0; mo1 = mn1;
#pragma unroll
        for (int n = 0; n < 8; n++) {
            o[n][0] *= corr0; o[n][1] *= corr0;
            o[n][2] *= corr1; o[n][3] *= corr1;
        }

        // O += P V : P C-fragment -> A-fragment via intra-quad shuffles.
        // A col (k) index t lives on lane (g<<2)|(t>>1), reg parity t&1.
        const int srcA = (lane & 28) | (t >> 1);
        const int srcB = srcA + 2;
        const bool odd = (t & 1);
#pragma unroll
        for (int j = 0; j < 8; j++) {          // k-step over kv (= S n-tile j)
            float s0 = __shfl_sync(0xffffffffu, s[j][0], srcA);
            float s1 = __shfl_sync(0xffffffffu, s[j][1], srcA);
            float s2 = __shfl_sync(0xffffffffu, s[j][2], srcA);
            float s3 = __shfl_sync(0xffffffffu, s[j][3], srcA);
            float u0 = __shfl_sync(0xffffffffu, s[j][0], srcB);
            float u1 = __shfl_sync(0xffffffffu, s[j][1], srcB);
            float u2 = __shfl_sync(0xffffffffu, s[j][2], srcB);
            float u3 = __shfl_sync(0xffffffffu, s[j][3], srcB);
            uint32_t a[4];
            a[0] = f2tf32(odd ? s1 : s0);   // P[g   ][8j + t]
            a[1] = f2tf32(odd ? s3 : s2);   // P[g+8 ][8j + t]
            a[2] = f2tf32(odd ? u1 : u0);   // P[g   ][8j + t + 4]
            a[3] = f2tf32(odd ? u3 : u2);   // P[g+8 ][8j + t + 4]
#pragma unroll
            for (int n = 0; n < 8; n++) {  // n-tile over d
                uint32_t b0 = Vs[(8 * j + t) * VSTR + 8 * n + g];
                uint32_t b1 = Vs[(8 * j + t + 4) * VSTR + 8 * n + g];
                mma_tf32(o[n], a, b0, b1);
            }
        }
    }

    // epilogue: ctx[b][seq][h*64 + col] = O / l
    const int b = bh >> 3;
    const int h = bh & 7;
    const int seq0 = qt * QT + w * 16 + g;
    const float inv0 = 1.f / l0;
    const float inv1 = 1.f / l1;
#pragma unroll
    for (int n = 0; n < 8; n++) {
        int col = h * HD + 8 * n + 2 * t;
        float2 r0 = make_float2(o[n][0] * inv0, o[n][1] * inv0);
        float2 r1 = make_float2(o[n][2] * inv1, o[n][3] * inv1);
        *(float2*)&g_ctx[(size_t)(b * NN + seq0) * DD + col] = r0;
        *(float2*)&g_ctx[(size_t)(b * NN + seq0 + 8) * DD + col] = r1;
    }
}

// ---------------------------------------------------------------------------
// Kernel 3: output projection (fp32 SIMT, proven).
// ---------------------------------------------------------------------------
__global__ __launch_bounds__(256) void proj_gemm(const float* __restrict__ w,
                                                 const float* __restrict__ bias,
                                                 float* __restrict__ out) {
    __shared__ float As[8][128];
    __shared__ float Bs[8][128];
    const int tid = threadIdx.x;
    const int m0 = blockIdx.y * 128;
    const int n0 = blockIdx.x * 128;
    const int tx = tid & 15;
    const int ty = tid >> 4;

    float acc[8][8];
#pragma unroll
    for (int i = 0; i < 8; i++)
#pragma unroll
        for (int j = 0; j < 8; j++) acc[i][j] = 0.f;

    const int lr = tid >> 1;
    const int lk4 = tid & 1;
    const float* xa = g_ctx + (m0 + lr) * DD + lk4 * 4;
    const float* wb = w + (n0 + lr) * DD + lk4 * 4;

    for (int k0 = 0; k0 < DD; k0 += 8) {
        float4 av = *(const float4*)(xa + k0);
        float4 bv = *(const float4*)(wb + k0);
        As[lk4 * 4 + 0][lr] = av.x; As[lk4 * 4 + 1][lr] = av.y;
        As[lk4 * 4 + 2][lr] = av.z; As[lk4 * 4 + 3][lr] = av.w;
        Bs[lk4 * 4 + 0][lr] = bv.x; Bs[lk4 * 4 + 1][lr] = bv.y;
        Bs[lk4 * 4 + 2][lr] = bv.z; Bs[lk4 * 4 + 3][lr] = bv.w;
        __syncthreads();
#pragma unroll
        for (int k = 0; k < 8; k++) {
            float4 a0 = *(const float4*)&As[k][ty * 8];
            float4 a1 = *(const float4*)&As[k][ty * 8 + 4];
            float4 b0 = *(const float4*)&Bs[k][tx * 8];
            float4 b1 = *(const float4*)&Bs[k][tx * 8 + 4];
            float a[8] = {a0.x, a0.y, a0.z, a0.w, a1.x, a1.y, a1.z, a1.w};
            float b[8] = {b0.x, b0.y, b0.z, b0.w, b1.x, b1.y, b1.z, b1.w};
#pragma unroll
            for (int i = 0; i < 8; i++)
#pragma unroll
                for (int j = 0; j < 8; j++) acc[i][j] += a[i] * b[j];
        }
        __syncthreads();
    }

#pragma unroll
    for (int i = 0; i < 8; i++) {
        int m = m0 + ty * 8 + i;
#pragma unroll
        for (int j = 0; j < 8; j++) {
            int n = n0 + tx * 8 + j;
            out[m * DD + n] = acc[i][j] + bias[n];
        }
    }
}

// ---------------------------------------------------------------------------

extern "C" void kernel_launch(void* const* d_in, const int* in_sizes, int n_in,
                              void* d_out, int out_size) {
    const float* x      = (const float*)d_in[0];
    const float* w_qkv  = (const float*)d_in[1];
    const float* w_proj = (const float*)d_in[2];
    const float* b_proj = (const float*)d_in[3];
    float* out = (float*)d_out;

    qkv_gemm<<<dim3(1536 / 128, MTOT / 128), 256>>>(x, w_qkv);
    attn_mma<<<dim3(NN / QT, NH), 256>>>();
    proj_gemm<<<dim3(DD / 128, MTOT / 128), 256>>>(w_proj, b_proj, out);
}

// round 4
// speedup vs baseline: 3.0515x; 1.4943x over previous
#include <cuda_runtime.h>
#include <cstdint>

#define BB 2
#define NN 4096
#define DD 512
#define HH 8
#define HD 64
#define NH (BB*HH)          // 16
#define MTOT (BB*NN)        // 8192
#define SCALE 0.125f

// Scratch (allocation-free rule: __device__ globals)
__device__ float g_q[NH * NN * HD];
__device__ float g_k[NH * NN * HD];
__device__ float g_v[NH * NN * HD];
__device__ float g_ctx[MTOT * DD];

// ---------------------------------------------------------------------------
// mma.sync tf32 primitives (m16n8k8, row.col, fp32 accum)
// ---------------------------------------------------------------------------
__device__ __forceinline__ uint32_t f2tf32(float f) {
    uint32_t r;
    asm("cvt.rna.tf32.f32 %0, %1;\n" : "=r"(r) : "f"(f));
    return r;
}

__device__ __forceinline__ void mma_tf32(float c[4], const uint32_t a[4],
                                         uint32_t b0, uint32_t b1) {
    asm volatile(
        "mma.sync.aligned.m16n8k8.row.col.f32.tf32.tf32.f32 "
        "{%0,%1,%2,%3}, {%4,%5,%6,%7}, {%8,%9}, {%0,%1,%2,%3};\n"
        : "+f"(c[0]), "+f"(c[1]), "+f"(c[2]), "+f"(c[3])
        : "r"(a[0]), "r"(a[1]), "r"(a[2]), "r"(a[3]), "r"(b0), "r"(b1));
}

// ---------------------------------------------------------------------------
// Shared tf32 GEMM mainloop: C[m][n] = sum_k A[m][k] * W[n][k]
// CTA tile 128x128, k-chunk 32, 8 warps (2x4), warp tile 64x32.
// Smem tiles [128][36] padded -> conflict-free fragment loads.
// acc[mi][ni][4] per thread.
// ---------------------------------------------------------------------------
#define GSTR 36

__device__ __forceinline__ void tf32_gemm_mainloop(
    const float* __restrict__ A, const float* __restrict__ W,
    int m0, int n0, int Kdim, float acc[4][4][4],
    uint32_t* As, uint32_t* Bs)
{
    const int tid  = threadIdx.x;
    const int lane = tid & 31;
    const int w    = tid >> 5;
    const int g    = lane >> 2;
    const int t    = lane & 3;
    const int wm   = (w & 1) * 64;   // warp m offset
    const int wn   = (w >> 1) * 32;  // warp n offset

    const int lrow = tid >> 1;        // 0..127
    const int lcb  = (tid & 1) * 16;  // col base 0 / 16

    const float* aptr = A + (size_t)(m0 + lrow) * Kdim + lcb;
    const float* bptr = W + (size_t)(n0 + lrow) * Kdim + lcb;

#pragma unroll
    for (int mi = 0; mi < 4; mi++)
#pragma unroll
        for (int ni = 0; ni < 4; ni++)
#pragma unroll
            for (int r = 0; r < 4; r++) acc[mi][ni][r] = 0.f;

    float4 pa[4], pb[4];
#pragma unroll
    for (int i = 0; i < 4; i++) {
        pa[i] = *(const float4*)(aptr + 4 * i);
        pb[i] = *(const float4*)(bptr + 4 * i);
    }

    const int nchunks = Kdim / 32;
    for (int kc = 0; kc < nchunks; kc++) {
        // stage regs -> smem (tf32)
#pragma unroll
        for (int i = 0; i < 4; i++) {
            uint4 ua, ub;
            ua.x = f2tf32(pa[i].x); ua.y = f2tf32(pa[i].y);
            ua.z = f2tf32(pa[i].z); ua.w = f2tf32(pa[i].w);
            ub.x = f2tf32(pb[i].x); ub.y = f2tf32(pb[i].y);
            ub.z = f2tf32(pb[i].z); ub.w = f2tf32(pb[i].w);
            *(uint4*)&As[lrow * GSTR + lcb + 4 * i] = ua;
            *(uint4*)&Bs[lrow * GSTR + lcb + 4 * i] = ub;
        }
        __syncthreads();

        if (kc + 1 < nchunks) {
            const float* an = aptr + (kc + 1) * 32;
            const float* bn = bptr + (kc + 1) * 32;
#pragma unroll
            for (int i = 0; i < 4; i++) {
                pa[i] = *(const float4*)(an + 4 * i);
                pb[i] = *(const float4*)(bn + 4 * i);
            }
        }

#pragma unroll
        for (int ks = 0; ks < 4; ks++) {
            uint32_t af[4][4];
#pragma unroll
            for (int mi = 0; mi < 4; mi++) {
                int mrow = wm + mi * 16 + g;
                af[mi][0] = As[mrow * GSTR + ks * 8 + t];
                af[mi][1] = As[(mrow + 8) * GSTR + ks * 8 + t];
                af[mi][2] = As[mrow * GSTR + ks * 8 + t + 4];
                af[mi][3] = As[(mrow + 8) * GSTR + ks * 8 + t + 4];
            }
#pragma unroll
            for (int ni = 0; ni < 4; ni++) {
                int nrow = wn + ni * 8 + g;
                uint32_t b0 = Bs[nrow * GSTR + ks * 8 + t];
                uint32_t b1 = Bs[nrow * GSTR + ks * 8 + t + 4];
#pragma unroll
                for (int mi = 0; mi < 4; mi++)
                    mma_tf32(acc[mi][ni], af[mi], b0, b1);
            }
        }
        __syncthreads();
    }
}

// ---------------------------------------------------------------------------
// Kernel 1: QKV GEMM (tf32 mma). Scatter epilogue into g_q/g_k/g_v.
// ---------------------------------------------------------------------------
__global__ __launch_bounds__(256, 1) void qkv_gemm_mma(
    const float* __restrict__ x, const float* __restrict__ wqkv)
{
    __shared__ uint32_t As[128 * GSTR];
    __shared__ uint32_t Bs[128 * GSTR];

    const int m0 = blockIdx.y * 128;
    const int n0 = blockIdx.x * 128;
    float acc[4][4][4];
    tf32_gemm_mainloop(x, wqkv, m0, n0, DD, acc, As, Bs);

    const int lane = threadIdx.x & 31;
    const int w    = threadIdx.x >> 5;
    const int g    = lane >> 2;
    const int t    = lane & 3;
    const int wm   = (w & 1) * 64;
    const int wn   = (w >> 1) * 32;

#pragma unroll
    for (int mi = 0; mi < 4; mi++) {
#pragma unroll
        for (int half = 0; half < 2; half++) {
            int m = m0 + wm + mi * 16 + g + half * 8;
            int b = m >> 12;
            int seq = m & (NN - 1);
#pragma unroll
            for (int ni = 0; ni < 4; ni++) {
                int n = n0 + wn + ni * 8 + 2 * t;
                int three = n >> 9;
                int h = (n >> 6) & 7;
                int hd = n & 63;
                float* dst = (three == 0) ? g_q : (three == 1) ? g_k : g_v;
                float2 val = half ? make_float2(acc[mi][ni][2], acc[mi][ni][3])
                                  : make_float2(acc[mi][ni][0], acc[mi][ni][1]);
                *(float2*)&dst[((size_t)(b * HH + h) * NN + seq) * HD + hd] = val;
            }
        }
    }
}

// ---------------------------------------------------------------------------
// Kernel 3: output projection (tf32 mma) + bias.
// ---------------------------------------------------------------------------
__global__ __launch_bounds__(256, 1) void proj_gemm_mma(
    const float* __restrict__ wproj, const float* __restrict__ bias,
    float* __restrict__ out)
{
    __shared__ uint32_t As[128 * GSTR];
    __shared__ uint32_t Bs[128 * GSTR];

    const int m0 = blockIdx.y * 128;
    const int n0 = blockIdx.x * 128;
    float acc[4][4][4];
    tf32_gemm_mainloop(g_ctx, wproj, m0, n0, DD, acc, As, Bs);

    const int lane = threadIdx.x & 31;
    const int w    = threadIdx.x >> 5;
    const int g    = lane >> 2;
    const int t    = lane & 3;
    const int wm   = (w & 1) * 64;
    const int wn   = (w >> 1) * 32;

#pragma unroll
    for (int mi = 0; mi < 4; mi++) {
#pragma unroll
        for (int ni = 0; ni < 4; ni++) {
            int n = n0 + wn + ni * 8 + 2 * t;
            float bx = bias[n], by = bias[n + 1];
            int m = m0 + wm + mi * 16 + g;
            *(float2*)&out[(size_t)m * DD + n] =
                make_float2(acc[mi][ni][0] + bx, acc[mi][ni][1] + by);
            *(float2*)&out[(size_t)(m + 8) * DD + n] =
                make_float2(acc[mi][ni][2] + bx, acc[mi][ni][3] + by);
        }
    }
}

// ---------------------------------------------------------------------------
// Kernel 2: flash attention with tf32 mma.sync (unchanged from round 3).
// ---------------------------------------------------------------------------
#define KT 64
#define QT 128
#define KSTR 68
#define VSTR 72

__global__ __launch_bounds__(256, 2) void attn_mma() {
    __shared__ uint32_t Ks[KT * KSTR];   // [kv][d] tf32
    __shared__ uint32_t Vs[KT * VSTR];   // [kv][d] tf32

    const int tid  = threadIdx.x;
    const int lane = tid & 31;
    const int w    = tid >> 5;
    const int g    = lane >> 2;
    const int t    = lane & 3;

    const int bh = blockIdx.y;
    const int qt = blockIdx.x;

    const float* qbase = g_q + (size_t)(bh * NN + qt * QT + w * 16) * HD;
    const float* kbase = g_k + (size_t)bh * NN * HD;
    const float* vbase = g_v + (size_t)bh * NN * HD;

    uint32_t qf[8][4];
#pragma unroll
    for (int j = 0; j < 8; j++) {
        qf[j][0] = f2tf32(qbase[g       * HD + 8 * j + t]     * SCALE);
        qf[j][1] = f2tf32(qbase[(g + 8) * HD + 8 * j + t]     * SCALE);
        qf[j][2] = f2tf32(qbase[g       * HD + 8 * j + t + 4] * SCALE);
        qf[j][3] = f2tf32(qbase[(g + 8) * HD + 8 * j + t + 4] * SCALE);
    }

    float o[8][4];
#pragma unroll
    for (int n = 0; n < 8; n++)
#pragma unroll
        for (int i = 0; i < 4; i++) o[n][i] = 0.f;
    float mo0 = -1e30f, mo1 = -1e30f;
    float l0 = 0.f, l1 = 0.f;

    for (int ktile = 0; ktile < NN / KT; ktile++) {
        __syncthreads();
        const float* kb = kbase + (size_t)ktile * KT * HD;
        const float* vb = vbase + (size_t)ktile * KT * HD;
#pragma unroll
        for (int it = 0; it < 4; it++) {
            int idx = tid + 256 * it;
            int r = idx >> 4;
            int c4 = idx & 15;
            float4 k4 = *(const float4*)(kb + r * HD + c4 * 4);
            uint4 kk;
            kk.x = f2tf32(k4.x); kk.y = f2tf32(k4.y);
            kk.z = f2tf32(k4.z); kk.w = f2tf32(k4.w);
            *(uint4*)&Ks[r * KSTR + c4 * 4] = kk;
            float4 v4 = *(const float4*)(vb + r * HD + c4 * 4);
            uint4 vv;
            vv.x = f2tf32(v4.x); vv.y = f2tf32(v4.y);
            vv.z = f2tf32(v4.z); vv.w = f2tf32(v4.w);
            *(uint4*)&Vs[r * VSTR + c4 * 4] = vv;
        }
        __syncthreads();

        float s[8][4];
#pragma unroll
        for (int n = 0; n < 8; n++)
#pragma unroll
            for (int i = 0; i < 4; i++) s[n][i] = 0.f;

#pragma unroll
        for (int j = 0; j < 8; j++) {
#pragma unroll
            for (int n = 0; n < 8; n++) {
                uint32_t b0 = Ks[(n * 8 + g) * KSTR + 8 * j + t];
                uint32_t b1 = Ks[(n * 8 + g) * KSTR + 8 * j + t + 4];
                mma_tf32(s[n], qf[j], b0, b1);
            }
        }

        float mx0 = -1e30f, mx1 = -1e30f;
#pragma unroll
        for (int n = 0; n < 8; n++) {
            mx0 = fmaxf(mx0, fmaxf(s[n][0], s[n][1]));
            mx1 = fmaxf(mx1, fmaxf(s[n][2], s[n][3]));
        }
        mx0 = fmaxf(mx0, __shfl_xor_sync(0xffffffffu, mx0, 1));
        mx0 = fmaxf(mx0, __shfl_xor_sync(0xffffffffu, mx0, 2));
        mx1 = fmaxf(mx1, __shfl_xor_sync(0xffffffffu, mx1, 1));
        mx1 = fmaxf(mx1, __shfl_xor_sync(0xffffffffu, mx1, 2));

        float mn0 = fmaxf(mo0, mx0);
        float mn1 = fmaxf(mo1, mx1);
        float corr0 = __expf(mo0 - mn0);
        float corr1 = __expf(mo1 - mn1);
        float rs0 = 0.f, rs1 = 0.f;
#pragma unroll
        for (int n = 0; n < 8; n++) {
            s[n][0] = __expf(s[n][0] - mn0);
            s[n][1] = __expf(s[n][1] - mn0);
            s[n][2] = __expf(s[n][2] - mn1);
            s[n][3] = __expf(s[n][3] - mn1);
            rs0 += s[n][0] + s[n][1];
            rs1 += s[n][2] + s[n][3];
        }
        rs0 += __shfl_xor_sync(0xffffffffu, rs0, 1);
        rs0 += __shfl_xor_sync(0xffffffffu, rs0, 2);
        rs1 += __shfl_xor_sync(0xffffffffu, rs1, 1);
        rs1 += __shfl_xor_sync(0xffffffffu, rs1, 2);
        l0 = l0 * corr0 + rs0;
        l1 = l1 * corr1 + rs1;
        mo0 = mn0; mo1 = mn1;
#pragma unroll
        for (int n = 0; n < 8; n++) {
            o[n][0] *= corr0; o[n][1] *= corr0;
            o[n][2] *= corr1; o[n][3] *= corr1;
        }

        const int srcA = (lane & 28) | (t >> 1);
        const int srcB = srcA + 2;
        const bool odd = (t & 1);
#pragma unroll
        for (int j = 0; j < 8; j++) {
            float s0 = __shfl_sync(0xffffffffu, s[j][0], srcA);
            float s1 = __shfl_sync(0xffffffffu, s[j][1], srcA);
            float s2 = __shfl_sync(0xffffffffu, s[j][2], srcA);
            float s3 = __shfl_sync(0xffffffffu, s[j][3], srcA);
            float u0 = __shfl_sync(0xffffffffu, s[j][0], srcB);
            float u1 = __shfl_sync(0xffffffffu, s[j][1], srcB);
            float u2 = __shfl_sync(0xffffffffu, s[j][2], srcB);
            float u3 = __shfl_sync(0xffffffffu, s[j][3], srcB);
            uint32_t a[4];
            a[0] = f2tf32(odd ? s1 : s0);
            a[1] = f2tf32(odd ? s3 : s2);
            a[2] = f2tf32(odd ? u1 : u0);
            a[3] = f2tf32(odd ? u3 : u2);
#pragma unroll
            for (int n = 0; n < 8; n++) {
                uint32_t b0 = Vs[(8 * j + t) * VSTR + 8 * n + g];
                uint32_t b1 = Vs[(8 * j + t + 4) * VSTR + 8 * n + g];
                mma_tf32(o[n], a, b0, b1);
            }
        }
    }

    const int b = bh >> 3;
    const int h = bh & 7;
    const int seq0 = qt * QT + w * 16 + g;
    const float inv0 = 1.f / l0;
    const float inv1 = 1.f / l1;
#pragma unroll
    for (int n = 0; n < 8; n++) {
        int col = h * HD + 8 * n + 2 * t;
        float2 r0 = make_float2(o[n][0] * inv0, o[n][1] * inv0);
        float2 r1 = make_float2(o[n][2] * inv1, o[n][3] * inv1);
        *(float2*)&g_ctx[(size_t)(b * NN + seq0) * DD + col] = r0;
        *(float2*)&g_ctx[(size_t)(b * NN + seq0 + 8) * DD + col] = r1;
    }
}

// ---------------------------------------------------------------------------

extern "C" void kernel_launch(void* const* d_in, const int* in_sizes, int n_in,
                              void* d_out, int out_size) {
    const float* x      = (const float*)d_in[0];
    const float* w_qkv  = (const float*)d_in[1];
    const float* w_proj = (const float*)d_in[2];
    const float* b_proj = (const float*)d_in[3];
    float* out = (float*)d_out;

    qkv_gemm_mma<<<dim3(1536 / 128, MTOT / 128), 256>>>(x, w_qkv);
    attn_mma<<<dim3(NN / QT, NH), 256>>>();
    proj_gemm_mma<<<dim3(DD / 128, MTOT / 128), 256>>>(w_proj, b_proj, out);
}

// round 5
// speedup vs baseline: 3.0787x; 1.0089x over previous
#include <cuda_runtime.h>
#include <cstdint>

#define BB 2
#define NN 4096
#define DD 512
#define HH 8
#define HD 64
#define NH (BB*HH)          // 16
#define MTOT (BB*NN)        // 8192
#define SCALE 0.125f

// Scratch (allocation-free rule: __device__ globals)
__device__ float g_q[NH * NN * HD];
__device__ float g_k[NH * NN * HD];
__device__ float g_v[NH * NN * HD];
__device__ float g_ctx[MTOT * DD];

// ---------------------------------------------------------------------------
// primitives
// ---------------------------------------------------------------------------
__device__ __forceinline__ uint32_t f2tf32(float f) {
    uint32_t r;
    asm("cvt.rna.tf32.f32 %0, %1;\n" : "=r"(r) : "f"(f));
    return r;
}

__device__ __forceinline__ void mma_tf32(float c[4], const uint32_t a[4],
                                         uint32_t b0, uint32_t b1) {
    asm volatile(
        "mma.sync.aligned.m16n8k8.row.col.f32.tf32.tf32.f32 "
        "{%0,%1,%2,%3}, {%4,%5,%6,%7}, {%8,%9}, {%0,%1,%2,%3};\n"
        : "+f"(c[0]), "+f"(c[1]), "+f"(c[2]), "+f"(c[3])
        : "r"(a[0]), "r"(a[1]), "r"(a[2]), "r"(a[3]), "r"(b0), "r"(b1));
}

__device__ __forceinline__ void cp_async16(uint32_t saddr, const void* gptr) {
    asm volatile("cp.async.cg.shared.global [%0], [%1], 16;\n"
                 :: "r"(saddr), "l"(gptr));
}
__device__ __forceinline__ void cp_commit() {
    asm volatile("cp.async.commit_group;\n");
}
__device__ __forceinline__ void cp_wait1() {
    asm volatile("cp.async.wait_group 1;\n");
}
__device__ __forceinline__ void cp_wait0() {
    asm volatile("cp.async.wait_group 0;\n");
}

// ---------------------------------------------------------------------------
// tf32 GEMM mainloop, cp.async double-buffered. C[m][n]=sum_k A[m][k]*W[n][k]
// CTA 128x128, k-chunk 32, 8 warps (2x4), warp tile 64x32.
// Stages hold raw fp32; cvt to tf32 at fragment load.
// ---------------------------------------------------------------------------
#define GSTR 36
#define STG_WORDS (128 * GSTR)

__device__ __forceinline__ void tf32_gemm_mainloop(
    const float* __restrict__ A, const float* __restrict__ W,
    int m0, int n0, float acc[4][4][4], float* As, float* Bs)
{
    const int tid  = threadIdx.x;
    const int lane = tid & 31;
    const int w    = tid >> 5;
    const int g    = lane >> 2;
    const int t    = lane & 3;
    const int wm   = (w & 1) * 64;
    const int wn   = (w >> 1) * 32;

    const int lrow = tid >> 1;
    const int lcb  = (tid & 1) * 16;

    const float* aptr = A + (size_t)(m0 + lrow) * DD + lcb;
    const float* bptr = W + (size_t)(n0 + lrow) * DD + lcb;
    const uint32_t sa = (uint32_t)__cvta_generic_to_shared(As + lrow * GSTR + lcb);
    const uint32_t sb = (uint32_t)__cvta_generic_to_shared(Bs + lrow * GSTR + lcb);

#pragma unroll
    for (int mi = 0; mi < 4; mi++)
#pragma unroll
        for (int ni = 0; ni < 4; ni++)
#pragma unroll
            for (int r = 0; r < 4; r++) acc[mi][ni][r] = 0.f;

    const int nchunks = DD / 32;   // 16

    // preload chunk 0 into stage 0
#pragma unroll
    for (int i = 0; i < 4; i++) {
        cp_async16(sa + (4 * i) * 4, aptr + 4 * i);
        cp_async16(sb + (4 * i) * 4, bptr + 4 * i);
    }
    cp_commit();

    for (int kc = 0; kc < nchunks; kc++) {
        const int cur = kc & 1;
        if (kc + 1 < nchunks) {
            const int nxt = 1 - cur;
            const float* an = aptr + (kc + 1) * 32;
            const float* bn = bptr + (kc + 1) * 32;
#pragma unroll
            for (int i = 0; i < 4; i++) {
                cp_async16(sa + (nxt * STG_WORDS + 4 * i) * 4, an + 4 * i);
                cp_async16(sb + (nxt * STG_WORDS + 4 * i) * 4, bn + 4 * i);
            }
            cp_commit();
            cp_wait1();            // current chunk's group complete
        } else {
            cp_wait0();
        }
        __syncthreads();

        const float* Ac = As + cur * STG_WORDS;
        const float* Bc = Bs + cur * STG_WORDS;
#pragma unroll
        for (int ks = 0; ks < 4; ks++) {
            uint32_t af[4][4];
#pragma unroll
            for (int mi = 0; mi < 4; mi++) {
                int mrow = wm + mi * 16 + g;
                af[mi][0] = f2tf32(Ac[mrow * GSTR + ks * 8 + t]);
                af[mi][1] = f2tf32(Ac[(mrow + 8) * GSTR + ks * 8 + t]);
                af[mi][2] = f2tf32(Ac[mrow * GSTR + ks * 8 + t + 4]);
                af[mi][3] = f2tf32(Ac[(mrow + 8) * GSTR + ks * 8 + t + 4]);
            }
#pragma unroll
            for (int ni = 0; ni < 4; ni++) {
                int nrow = wn + ni * 8 + g;
                uint32_t b0 = f2tf32(Bc[nrow * GSTR + ks * 8 + t]);
                uint32_t b1 = f2tf32(Bc[nrow * GSTR + ks * 8 + t + 4]);
#pragma unroll
                for (int mi = 0; mi < 4; mi++)
                    mma_tf32(acc[mi][ni], af[mi], b0, b1);
            }
        }
        __syncthreads();   // stage reusable for kc+2's issue
    }
}

#define GEMM_SMEM (4 * STG_WORDS * 4)   // 2 stages x (A+B) x fp32  = 73728 B

// ---------------------------------------------------------------------------
// Kernel 1: QKV GEMM (tf32 mma + cp.async). Scatter epilogue into g_q/g_k/g_v.
// ---------------------------------------------------------------------------
__global__ __launch_bounds__(256, 2) void qkv_gemm_mma(
    const float* __restrict__ x, const float* __restrict__ wqkv)
{
    extern __shared__ float sm[];
    float* As = sm;
    float* Bs = sm + 2 * STG_WORDS;

    const int m0 = blockIdx.y * 128;
    const int n0 = blockIdx.x * 128;
    float acc[4][4][4];
    tf32_gemm_mainloop(x, wqkv, m0, n0, acc, As, Bs);

    const int lane = threadIdx.x & 31;
    const int w    = threadIdx.x >> 5;
    const int g    = lane >> 2;
    const int t    = lane & 3;
    const int wm   = (w & 1) * 64;
    const int wn   = (w >> 1) * 32;

#pragma unroll
    for (int mi = 0; mi < 4; mi++) {
#pragma unroll
        for (int half = 0; half < 2; half++) {
            int m = m0 + wm + mi * 16 + g + half * 8;
            int b = m >> 12;
            int seq = m & (NN - 1);
#pragma unroll
            for (int ni = 0; ni < 4; ni++) {
                int n = n0 + wn + ni * 8 + 2 * t;
                int three = n >> 9;
                int h = (n >> 6) & 7;
                int hd = n & 63;
                float* dst = (three == 0) ? g_q : (three == 1) ? g_k : g_v;
                float2 val = half ? make_float2(acc[mi][ni][2], acc[mi][ni][3])
                                  : make_float2(acc[mi][ni][0], acc[mi][ni][1]);
                *(float2*)&dst[((size_t)(b * HH + h) * NN + seq) * HD + hd] = val;
            }
        }
    }
}

// ---------------------------------------------------------------------------
// Kernel 3: output projection (tf32 mma + cp.async) + bias.
// ---------------------------------------------------------------------------
__global__ __launch_bounds__(256, 2) void proj_gemm_mma(
    const float* __restrict__ wproj, const float* __restrict__ bias,
    float* __restrict__ out)
{
    extern __shared__ float sm[];
    float* As = sm;
    float* Bs = sm + 2 * STG_WORDS;

    const int m0 = blockIdx.y * 128;
    const int n0 = blockIdx.x * 128;
    float acc[4][4][4];
    tf32_gemm_mainloop(g_ctx, wproj, m0, n0, acc, As, Bs);

    const int lane = threadIdx.x & 31;
    const int w    = threadIdx.x >> 5;
    const int g    = lane >> 2;
    const int t    = lane & 3;
    const int wm   = (w & 1) * 64;
    const int wn   = (w >> 1) * 32;

#pragma unroll
    for (int mi = 0; mi < 4; mi++) {
#pragma unroll
        for (int ni = 0; ni < 4; ni++) {
            int n = n0 + wn + ni * 8 + 2 * t;
            float bx = bias[n], by = bias[n + 1];
            int m = m0 + wm + mi * 16 + g;
            *(float2*)&out[(size_t)m * DD + n] =
                make_float2(acc[mi][ni][0] + bx, acc[mi][ni][1] + by);
            *(float2*)&out[(size_t)(m + 8) * DD + n] =
                make_float2(acc[mi][ni][2] + bx, acc[mi][ni][3] + by);
        }
    }
}

// ---------------------------------------------------------------------------
// Kernel 2: flash attention with tf32 mma.sync.
// K stored PAIR-INTERLEAVED: Kp[r][j*8 + t*2 + h] = K[r][8j + t + 4h]
// -> S-phase B fragments load as one LDS.64 (conflict-free, stride 72).
// V stored [kv][d] stride 72 (unchanged).
// ---------------------------------------------------------------------------
#define KT 64
#define QT 128
#define KP 72
#define VSTR 72

__global__ __launch_bounds__(256, 2) void attn_mma() {
    __shared__ uint32_t Ks[KT * KP];
    __shared__ uint32_t Vs[KT * VSTR];

    const int tid  = threadIdx.x;
    const int lane = tid & 31;
    const int w    = tid >> 5;
    const int g    = lane >> 2;
    const int t    = lane & 3;

    const int bh = blockIdx.y;
    const int qt = blockIdx.x;

    const float* qbase = g_q + (size_t)(bh * NN + qt * QT + w * 16) * HD;
    const float* kbase = g_k + (size_t)bh * NN * HD;
    const float* vbase = g_v + (size_t)bh * NN * HD;

    uint32_t qf[8][4];
#pragma unroll
    for (int j = 0; j < 8; j++) {
        qf[j][0] = f2tf32(qbase[g       * HD + 8 * j + t]     * SCALE);
        qf[j][1] = f2tf32(qbase[(g + 8) * HD + 8 * j + t]     * SCALE);
        qf[j][2] = f2tf32(qbase[g       * HD + 8 * j + t + 4] * SCALE);
        qf[j][3] = f2tf32(qbase[(g + 8) * HD + 8 * j + t + 4] * SCALE);
    }

    float o[8][4];
#pragma unroll
    for (int n = 0; n < 8; n++)
#pragma unroll
        for (int i = 0; i < 4; i++) o[n][i] = 0.f;
    float mo0 = -1e30f, mo1 = -1e30f;
    float l0 = 0.f, l1 = 0.f;

    for (int ktile = 0; ktile < NN / KT; ktile++) {
        __syncthreads();
        const float* kb = kbase + (size_t)ktile * KT * HD;
        const float* vb = vbase + (size_t)ktile * KT * HD;
#pragma unroll
        for (int it = 0; it < 4; it++) {
            int idx = tid + 256 * it;
            int r = idx >> 4;             // kv row 0..63
            int c4 = idx & 15;            // float4 col
            float4 k4 = *(const float4*)(kb + r * HD + c4 * 4);
            // pair-interleaved K store: col = 4*c4+e ; j=c4>>1, h=c4&1, t=e
            int jj = c4 >> 1, hh = c4 & 1;
            uint32_t* kdst = &Ks[r * KP + jj * 8 + hh];
            kdst[0] = f2tf32(k4.x);
            kdst[2] = f2tf32(k4.y);
            kdst[4] = f2tf32(k4.z);
            kdst[6] = f2tf32(k4.w);
            float4 v4 = *(const float4*)(vb + r * HD + c4 * 4);
            uint4 vv;
            vv.x = f2tf32(v4.x); vv.y = f2tf32(v4.y);
            vv.z = f2tf32(v4.z); vv.w = f2tf32(v4.w);
            *(uint4*)&Vs[r * VSTR + c4 * 4] = vv;
        }
        __syncthreads();

        float s[8][4];
#pragma unroll
        for (int n = 0; n < 8; n++)
#pragma unroll
            for (int i = 0; i < 4; i++) s[n][i] = 0.f;

#pragma unroll
        for (int j = 0; j < 8; j++) {
#pragma unroll
            for (int n = 0; n < 8; n++) {
                uint2 bp = *(const uint2*)&Ks[(n * 8 + g) * KP + j * 8 + t * 2];
                mma_tf32(s[n], qf[j], bp.x, bp.y);
            }
        }

        float mx0 = -1e30f, mx1 = -1e30f;
#pragma unroll
        for (int n = 0; n < 8; n++) {
            mx0 = fmaxf(mx0, fmaxf(s[n][0], s[n][1]));
            mx1 = fmaxf(mx1, fmaxf(s[n][2], s[n][3]));
        }
        mx0 = fmaxf(mx0, __shfl_xor_sync(0xffffffffu, mx0, 1));
        mx0 = fmaxf(mx0, __shfl_xor_sync(0xffffffffu, mx0, 2));
        mx1 = fmaxf(mx1, __shfl_xor_sync(0xffffffffu, mx1, 1));
        mx1 = fmaxf(mx1, __shfl_xor_sync(0xffffffffu, mx1, 2));

        float mn0 = fmaxf(mo0, mx0);
        float mn1 = fmaxf(mo1, mx1);
        float corr0 = __expf(mo0 - mn0);
        float corr1 = __expf(mo1 - mn1);
        float rs0 = 0.f, rs1 = 0.f;
#pragma unroll
        for (int n = 0; n < 8; n++) {
            s[n][0] = __expf(s[n][0] - mn0);
            s[n][1] = __expf(s[n][1] - mn0);
            s[n][2] = __expf(s[n][2] - mn1);
            s[n][3] = __expf(s[n][3] - mn1);
            rs0 += s[n][0] + s[n][1];
            rs1 += s[n][2] + s[n][3];
        }
        rs0 += __shfl_xor_sync(0xffffffffu, rs0, 1);
        rs0 += __shfl_xor_sync(0xffffffffu, rs0, 2);
        rs1 += __shfl_xor_sync(0xffffffffu, rs1, 1);
        rs1 += __shfl_xor_sync(0xffffffffu, rs1, 2);
        l0 = l0 * corr0 + rs0;
        l1 = l1 * corr1 + rs1;
        mo0 = mn0; mo1 = mn1;
#pragma unroll
        for (int n = 0; n < 8; n++) {
            o[n][0] *= corr0; o[n][1] *= corr0;
            o[n][2] *= corr1; o[n][3] *= corr1;
        }

        const int srcA = (lane & 28) | (t >> 1);
        const int srcB = srcA + 2;
        const bool odd = (t & 1);
#pragma unroll
        for (int j = 0; j < 8; j++) {
            float s0 = __shfl_sync(0xffffffffu, s[j][0], srcA);
            float s1 = __shfl_sync(0xffffffffu, s[j][1], srcA);
            float s2 = __shfl_sync(0xffffffffu, s[j][2], srcA);
            float s3 = __shfl_sync(0xffffffffu, s[j][3], srcA);
            float u0 = __shfl_sync(0xffffffffu, s[j][0], srcB);
            float u1 = __shfl_sync(0xffffffffu, s[j][1], srcB);
            float u2 = __shfl_sync(0xffffffffu, s[j][2], srcB);
            float u3 = __shfl_sync(0xffffffffu, s[j][3], srcB);
            uint32_t a[4];
            a[0] = f2tf32(odd ? s1 : s0);
            a[1] = f2tf32(odd ? s3 : s2);
            a[2] = f2tf32(odd ? u1 : u0);
            a[3] = f2tf32(odd ? u3 : u2);
#pragma unroll
            for (int n = 0; n < 8; n++) {
                uint32_t b0 = Vs[(8 * j + t) * VSTR + 8 * n + g];
                uint32_t b1 = Vs[(8 * j + t + 4) * VSTR + 8 * n + g];
                mma_tf32(o[n], a, b0, b1);
            }
        }
    }

    const int b = bh >> 3;
    const int h = bh & 7;
    const int seq0 = qt * QT + w * 16 + g;
    const float inv0 = 1.f / l0;
    const float inv1 = 1.f / l1;
#pragma unroll
    for (int n = 0; n < 8; n++) {
        int col = h * HD + 8 * n + 2 * t;
        float2 r0 = make_float2(o[n][0] * inv0, o[n][1] * inv0);
        float2 r1 = make_float2(o[n][2] * inv1, o[n][3] * inv1);
        *(float2*)&g_ctx[(size_t)(b * NN + seq0) * DD + col] = r0;
        *(float2*)&g_ctx[(size_t)(b * NN + seq0 + 8) * DD + col] = r1;
    }
}

// ---------------------------------------------------------------------------

extern "C" void kernel_launch(void* const* d_in, const int* in_sizes, int n_in,
                              void* d_out, int out_size) {
    const float* x      = (const float*)d_in[0];
    const float* w_qkv  = (const float*)d_in[1];
    const float* w_proj = (const float*)d_in[2];
    const float* b_proj = (const float*)d_in[3];
    float* out = (float*)d_out;

    static int cfg_done = 0;
    if (!cfg_done) {
        cudaFuncSetAttribute(qkv_gemm_mma,
                             cudaFuncAttributeMaxDynamicSharedMemorySize, GEMM_SMEM);
        cudaFuncSetAttribute(proj_gemm_mma,
                             cudaFuncAttributeMaxDynamicSharedMemorySize, GEMM_SMEM);
        cfg_done = 1;
    }

    qkv_gemm_mma<<<dim3(1536 / 128, MTOT / 128), 256, GEMM_SMEM>>>(x, w_qkv);
    attn_mma<<<dim3(NN / QT, NH), 256>>>();
    proj_gemm_mma<<<dim3(DD / 128, MTOT / 128), 256, GEMM_SMEM>>>(w_proj, b_proj, out);
}